// round 16
// baseline (speedup 1.0000x reference)
#include <cuda_runtime.h>

// Layout constants (columns within the 208-wide feature dim)
#define NCOLS        208
#define OPCODE_START 88
// opcode offsets
#define OP_JMP 2
#define OP_BZ  4
#define OP_BNZ 5

#define SCAN_GRID    512
#define SCAN_THREADS 256

__device__ unsigned g_partials[SCAN_GRID];
// Monotone arrival counter: zero at module load, NEVER reset. Each scan
// execution adds exactly SCAN_GRID, so the last arrival of any run satisfies
// (ticket+1) % SCAN_GRID == 0. Deterministic across correctness run + replays.
__device__ unsigned g_arrive;
__device__ unsigned g_flags;

// Kernel 1: opcode scan. Each block ORs its rows' flags, stores its partial
// unconditionally (-> no reset kernel); the LAST block to arrive reduces the
// partials into g_flags. Every block fires the PDL trigger when done, so the
// dependent apply kernel's griddepcontrol.wait releases as soon as g_flags is
// globally visible. No spin-wait anywhere -> no deadlock risk.
__global__ void __launch_bounds__(SCAN_THREADS)
scan_kernel(const float* __restrict__ x, int nrows)
{
    __shared__ unsigned s_warp[SCAN_THREADS / 32];
    __shared__ unsigned s_last;

    const int tid = threadIdx.x;
    unsigned f = 0u;
    for (int r = blockIdx.x * SCAN_THREADS + tid; r < nrows;
         r += SCAN_GRID * SCAN_THREADS) {
        const float* xr = x + (size_t)r * NCOLS + OPCODE_START;
        if (xr[OP_JMP] > 0.5f) f |= 1u;
        if (xr[OP_BZ]  > 0.5f) f |= 2u;
        if (xr[OP_BNZ] > 0.5f) f |= 4u;
    }
    f = __reduce_or_sync(0xFFFFFFFFu, f);
    if ((tid & 31) == 0) s_warp[tid >> 5] = f;
    __syncthreads();

    if (tid == 0) {
        unsigned bf = 0u;
        #pragma unroll
        for (int w = 0; w < SCAN_THREADS / 32; w++) bf |= s_warp[w];
        g_partials[blockIdx.x] = bf;
        __threadfence();                 // release partial before arriving
        unsigned ticket;
        asm volatile("atom.global.acq_rel.gpu.add.u32 %0, [%1], %2;"
                     : "=r"(ticket) : "l"(&g_arrive), "r"(1u) : "memory");
        s_last = (((ticket + 1u) % SCAN_GRID) == 0u) ? 1u : 0u;
    }
    __syncthreads();

    if (s_last) {
        if (tid < 32) {                  // last block: warp 0 reduces partials
            unsigned acc = 0u;
            #pragma unroll 4
            for (int i = tid; i < SCAN_GRID; i += 32) acc |= g_partials[i];
            acc = __reduce_or_sync(0xFFFFFFFFu, acc);
            if (tid == 0) {
                g_flags = acc;           // unconditional store, no reset needed
                __threadfence();         // flags visible before our trigger
            }
        }
        __syncthreads();
    }
    // PDL trigger: dependent grid's wait releases once ALL blocks trigger.
    // The flag-writing block triggers only after g_flags is fenced out.
    cudaTriggerProgrammaticLaunchCompletion();
}

// Kernel 2: one warp per row. Launched with PDL so it starts concurrently
// with scan: it issues its bulk loads FIRST (no dependency), then
// griddepcontrol.wait's for scan, then reads g_flags and patches.
// The 24 operand floats (AX/PC/IMM) are harvested from the already-loaded v1
// registers via shuffles (AX: lane8.w, lane9.xyzw, lane10.xyz | PC: lane10.w,
// lane11.xyzw, lane12.xyz | IMM: lane16.w, lane17.xyzw, lane18.xyz), so no
// memory is touched twice and .cs streaming hints are safe everywhere.
__global__ void __launch_bounds__(256)
apply_kernel(const float* __restrict__ x, float* __restrict__ y, int nrows)
{
    const int gw   = (blockIdx.x * blockDim.x + threadIdx.x) >> 5;
    const int lane = threadIdx.x & 31;
    if (gw >= nrows) {
        cudaGridDependencySynchronize();
        return;
    }

    const float4* xv = (const float4*)(x + (size_t)gw * NCOLS);
    float4*       yv = (float4*)(y + (size_t)gw * NCOLS);

    // Bulk row copy: 52 float4 chunks (208 floats), streaming loads.
    // Issued BEFORE the PDL wait so the memory ramp overlaps the scan.
    float4 v0 = __ldcs(xv + lane);
    float4 v1 = make_float4(0.f, 0.f, 0.f, 0.f);
    if (lane < 20) v1 = __ldcs(xv + 32 + lane);

    // Wait for scan grid's triggers; its g_flags write is then visible.
    cudaGridDependencySynchronize();
    const unsigned flags = g_flags;

    if (flags != 0u) {
        const unsigned m = 0xFFFFFFFFu;
        // Operand broadcast straight out of v1 registers.
        float a0 = __shfl_sync(m, v1.w, 8);
        float a1 = __shfl_sync(m, v1.x, 9),  a2 = __shfl_sync(m, v1.y, 9);
        float a3 = __shfl_sync(m, v1.z, 9),  a4 = __shfl_sync(m, v1.w, 9);
        float a5 = __shfl_sync(m, v1.x, 10), a6 = __shfl_sync(m, v1.y, 10);
        float a7 = __shfl_sync(m, v1.z, 10);

        float p0 = __shfl_sync(m, v1.w, 10);
        float p1 = __shfl_sync(m, v1.x, 11), p2 = __shfl_sync(m, v1.y, 11);
        float p3 = __shfl_sync(m, v1.z, 11), p4 = __shfl_sync(m, v1.w, 11);
        float p5 = __shfl_sync(m, v1.x, 12), p6 = __shfl_sync(m, v1.y, 12);
        float p7 = __shfl_sync(m, v1.z, 12);

        float i0 = __shfl_sync(m, v1.w, 16);
        float i1 = __shfl_sync(m, v1.x, 17), i2 = __shfl_sync(m, v1.y, 17);
        float i3 = __shfl_sync(m, v1.z, 17), i4 = __shfl_sync(m, v1.w, 17);
        float i5 = __shfl_sync(m, v1.x, 18), i6 = __shfl_sync(m, v1.y, 18);
        float i7 = __shfl_sync(m, v1.z, 18);

        // Sequential n=0..7 accumulation mirrors XLA's unrolled contraction.
        // 16^n is a power of two -> multiplies exact; only add order matters.
        const float aops[8] = {a0,a1,a2,a3,a4,a5,a6,a7};
        const float pops[8] = {p0,p1,p2,p3,p4,p5,p6,p7};
        const float iops[8] = {i0,i1,i2,i3,i4,i5,i6,i7};
        float imm = 0.f, pc = 0.f;
        int   ax  = 0;
        #pragma unroll
        for (int n = 0; n < 8; n++) {
            const float pw = (float)(1 << (4 * n));
            imm = __fadd_rn(imm, __fmul_rn(iops[n], pw));
            pc  = __fadd_rn(pc,  __fmul_rn(pops[n], pw));
            ax += (int)aops[n] * (1 << (4 * n));   // trunc == astype(int32)
        }

        const bool jmp = (flags & 1u) != 0u;
        const bool bz  = (flags & 2u) != 0u;
        const bool bnz = (flags & 4u) != 0u;
        const bool az  = (ax == 0);

        float new_pc, bt;
        const float pc8 = __fadd_rn(pc, 8.0f);
        if (jmp)      { new_pc = imm;            bt = 1.0f; }
        else if (bz)  { new_pc = az ? imm : pc8; bt = az ? 1.0f : 0.0f; }
        else if (bnz) { new_pc = az ? pc8 : imm; bt = az ? 0.0f : 1.0f; }
        else          { new_pc = pc;             bt = 0.0f; /* unreachable */ }

        const int v = (int)new_pc;   // round-toward-zero == astype(int32)

        // Patch PC nibbles: cols 171..178 -> chunks 42(e3), 43(e0..3),
        // 44(e0..2); branch_taken col 203 -> chunk 50(e3).
        if (lane == 10) {
            v1.w = (float)(v & 15);
        } else if (lane == 11) {
            v1.x = (float)((v >> 4)  & 15);
            v1.y = (float)((v >> 8)  & 15);
            v1.z = (float)((v >> 12) & 15);
            v1.w = (float)((v >> 16) & 15);
        } else if (lane == 12) {
            v1.x = (float)((v >> 20) & 15);
            v1.y = (float)((v >> 24) & 15);
            v1.z = (float)((v >> 28) & 15);
        } else if (lane == 18) {
            v1.w = bt;
        }
    }
    // flags == 0: verbatim copy (reference early-return)

    __stcs(yv + lane, v0);
    if (lane < 20) __stcs(yv + 32 + lane, v1);
}

extern "C" void kernel_launch(void* const* d_in, const int* in_sizes, int n_in,
                              void* d_out, int out_size) {
    const float* x = (const float*)d_in[0];
    float*       y = (float*)d_out;
    int nrows = in_sizes[0] / NCOLS;

    scan_kernel<<<SCAN_GRID, SCAN_THREADS>>>(x, nrows);

    // Apply launched with programmatic dependent launch: it may begin while
    // scan is still running; its griddepcontrol.wait gates only the g_flags
    // read, so the bulk loads overlap the scan entirely.
    int rows_per_block = 256 / 32;
    int blocks = (nrows + rows_per_block - 1) / rows_per_block;

    cudaLaunchAttribute attrs[1];
    attrs[0].id = cudaLaunchAttributeProgrammaticStreamSerialization;
    attrs[0].val.programmaticStreamSerializationAllowed = 1;

    cudaLaunchConfig_t cfg = {};
    cfg.gridDim  = dim3((unsigned)blocks, 1, 1);
    cfg.blockDim = dim3(256, 1, 1);
    cfg.dynamicSmemBytes = 0;
    cfg.stream = 0;
    cfg.attrs = attrs;
    cfg.numAttrs = 1;

    cudaLaunchKernelEx(&cfg, apply_kernel, x, y, nrows);
}